// round 1
// baseline (speedup 1.0000x reference)
#include <cuda_runtime.h>

// UpsampleLayer2D: x[B,R,C,64] -> out[B,2R,2C,16]
// out[b, ro, co, c] = x[b, ro%R, co%C, 4c + q],  q = 2*(ro>=R) + (co>=C)
//
// Scheme: 4 threads per input pixel. Thread t loads input channels
// [16t, 16t+16) as 4 contiguous float4 (warp read = 2KB contiguous),
// then scatters one float4 per quadrant (channels 4t..4t+3), so each
// quadrant store is 512B contiguous per warp.

#define B_  32
#define R_  200
#define C_  200
#define CIN 64
#define COUT 16
#define NPIX (B_ * R_ * C_)          // 1,280,000
#define NTHREADS_TOTAL (NPIX * 4)    // 5,120,000

__device__ __forceinline__ float comp(const float4& v, int q) {
    switch (q) {
        case 0:  return v.x;
        case 1:  return v.y;
        case 2:  return v.z;
        default: return v.w;
    }
}

__global__ __launch_bounds__(256)
void upsample_kernel(const float* __restrict__ in, float* __restrict__ out) {
    int idx = blockIdx.x * blockDim.x + threadIdx.x;
    if (idx >= NTHREADS_TOTAL) return;

    const int t   = idx & 3;       // channel-group role within pixel
    const int pix = idx >> 2;      // linear input pixel

    const int col = pix % C_;
    const int tmp = pix / C_;
    const int row = tmp % R_;
    const int b   = tmp / R_;

    // Contiguous 64B read: channels [16t, 16t+16)
    const float4* ip = reinterpret_cast<const float4*>(in) + (size_t)pix * (CIN / 4) + t * 4;
    float4 v0 = ip[0];
    float4 v1 = ip[1];
    float4 v2 = ip[2];
    float4 v3 = ip[3];

    float4* op = reinterpret_cast<float4*>(out);

    #pragma unroll
    for (int q = 0; q < 4; q++) {
        const int ro = row + R_ * (q >> 1);
        const int co = col + C_ * (q & 1);
        // output pixel base in float4 units: 16 floats = 4 float4 per pixel
        const size_t obase = (((size_t)b * (2 * R_) + ro) * (2 * C_) + co) * (COUT / 4) + t;
        // channels 4t..4t+3 of quadrant q come from input channels 16t+q, 16t+4+q, ...
        float4 w;
        w.x = comp(v0, q);
        w.y = comp(v1, q);
        w.z = comp(v2, q);
        w.w = comp(v3, q);
        op[obase] = w;
    }
}

extern "C" void kernel_launch(void* const* d_in, const int* in_sizes, int n_in,
                              void* d_out, int out_size) {
    const float* x = (const float*)d_in[0];
    float* out = (float*)d_out;
    const int threads = 256;
    const int blocks = (NTHREADS_TOTAL + threads - 1) / threads;  // 20000
    upsample_kernel<<<blocks, threads>>>(x, out);
}

// round 2
// speedup vs baseline: 1.0020x; 1.0020x over previous
#include <cuda_runtime.h>

// UpsampleLayer2D: x[B,R,C,64] -> out[B,2R,2C,16]
// out[b, ro, co, c] = x[b, ro%R, co%C, 4c + q],  q = 2*(ro>=R) + (co>=C)
//
// Scheme: 4 threads per input pixel (role t), thread t loads input channels
// [16t,16t+16) as 4 contiguous float4 (warp read = 2KB contiguous), scatters
// one float4 per quadrant (warp store = 512B contiguous per quadrant).
// R2: 2 pixel-groups per thread (8 front-batched LDG.128 -> higher MLP),
// streaming cache hints (__ldcs / __stcs) since every byte is single-touch.

#define B_  32
#define R_  200
#define C_  200
#define CIN 64
#define COUT 16
#define NPIX (B_ * R_ * C_)          // 1,280,000
#define NGROUPS (NPIX * 4)           // 5,120,000 (pixel,role) pairs
#define HALF (NGROUPS / 2)           // 2,560,000

__device__ __forceinline__ float comp(const float4& v, int q) {
    switch (q) {
        case 0:  return v.x;
        case 1:  return v.y;
        case 2:  return v.z;
        default: return v.w;
    }
}

__device__ __forceinline__ void scatter(int idx, const float4 v[4],
                                        float4* __restrict__ op) {
    const int t   = idx & 3;
    const int pix = idx >> 2;
    const int col = pix % C_;
    const int tmp = pix / C_;
    const int row = tmp % R_;
    const int b   = tmp / R_;

    #pragma unroll
    for (int q = 0; q < 4; q++) {
        const int ro = row + R_ * (q >> 1);
        const int co = col + C_ * (q & 1);
        const size_t obase =
            (((size_t)b * (2 * R_) + ro) * (2 * C_) + co) * (COUT / 4) + t;
        float4 w;
        w.x = comp(v[0], q);
        w.y = comp(v[1], q);
        w.z = comp(v[2], q);
        w.w = comp(v[3], q);
        __stcs(op + obase, w);
    }
}

__global__ __launch_bounds__(256)
void upsample_kernel(const float* __restrict__ in, float* __restrict__ out) {
    const int idx = blockIdx.x * blockDim.x + threadIdx.x;
    if (idx >= HALF) return;
    const int idx2 = idx + HALF;

    const float4* ibase = reinterpret_cast<const float4*>(in);
    float4* op = reinterpret_cast<float4*>(out);

    // Front-batch all 8 LDG.128 for maximum memory-level parallelism.
    const float4* ip0 = ibase + ((size_t)(idx  >> 2)) * (CIN / 4) + (idx  & 3) * 4;
    const float4* ip1 = ibase + ((size_t)(idx2 >> 2)) * (CIN / 4) + (idx2 & 3) * 4;

    float4 a[4], b[4];
    a[0] = __ldcs(ip0 + 0);
    a[1] = __ldcs(ip0 + 1);
    a[2] = __ldcs(ip0 + 2);
    a[3] = __ldcs(ip0 + 3);
    b[0] = __ldcs(ip1 + 0);
    b[1] = __ldcs(ip1 + 1);
    b[2] = __ldcs(ip1 + 2);
    b[3] = __ldcs(ip1 + 3);

    scatter(idx,  a, op);
    scatter(idx2, b, op);
}

extern "C" void kernel_launch(void* const* d_in, const int* in_sizes, int n_in,
                              void* d_out, int out_size) {
    const float* x = (const float*)d_in[0];
    float* out = (float*)d_out;
    const int threads = 256;
    const int blocks = (HALF + threads - 1) / threads;  // 10000
    upsample_kernel<<<blocks, threads>>>(x, out);
}